// round 3
// baseline (speedup 1.0000x reference)
#include <cuda_runtime.h>
#include <cstdint>

#define D 128
#define NMAX 100000
#define EMAX 800000

// -------- scratch (device globals; no allocations allowed) --------
__device__ float g_h[(size_t)NMAX * D];   // x @ W^T
__device__ float g_deg[NMAX];
__device__ float g_dinv[NMAX];
__device__ int   g_rows[EMAX];
__device__ int   g_cols[EMAX];
__device__ float g_sum[D];
__device__ float g_sumsq[D];
__device__ float g_mean[D];
__device__ float g_scale[D];
__device__ int   g_is64;

// -------- edge dtype detection (int64 vs int32) --------
// Values are node ids in [0, 1e5) << 2^31. If the buffer is int64, every odd
// 32-bit word (high half) is zero. If it is int32, odd words are random node
// ids (P(word==0) ~ 1e-5 each). Reading 512B is safe for either layout.
__global__ void detect_kernel(const unsigned int* __restrict__ w) {
    if (threadIdx.x == 0) {
        int is64 = 1;
        for (int i = 1; i < 128; i += 2)
            if (w[i] != 0u) { is64 = 0; break; }
        g_is64 = is64;
    }
}

__global__ void convert_kernel(const void* __restrict__ ei, int E) {
    int e = blockIdx.x * blockDim.x + threadIdx.x;
    if (e >= E) return;
    if (g_is64) {
        const long long* p = (const long long*)ei;
        g_rows[e] = (int)p[e];
        g_cols[e] = (int)p[(size_t)E + e];
    } else {
        const int* p = (const int*)ei;
        g_rows[e] = p[e];
        g_cols[e] = p[(size_t)E + e];
    }
}

// -------- zero scratch --------
__global__ void zero_kernel(int n) {
    int i = blockIdx.x * blockDim.x + threadIdx.x;
    if (i < n) g_deg[i] = 0.f;
    if (i < D) { g_sum[i] = 0.f; g_sumsq[i] = 0.f; }
}

// -------- degree over destination (col) --------
__global__ void deg_kernel(int E) {
    int e = blockIdx.x * blockDim.x + threadIdx.x;
    if (e < E) atomicAdd(&g_deg[g_cols[e]], 1.0f);
}

__global__ void dinv_kernel(int n) {
    int i = blockIdx.x * blockDim.x + threadIdx.x;
    if (i < n) {
        float d = g_deg[i];
        g_dinv[i] = (d > 0.f) ? rsqrtf(d) : 0.f;
    }
}

// -------- GEMM: h = x @ W^T  (W: [D,D] row-major; h[i][j] = sum_k x[i][k]*W[j][k]) --------
// 256 threads = 2 teams of 128; thread j computes output column j for 8 rows.
// W transposed into smem with stride-129 padding (conflict-free LDS both ways).
#define GEMM_SMEM ((128 * 129 + 16 * 128) * 4)
__global__ void gemm_kernel(const float* __restrict__ x, const float* __restrict__ W, int n) {
    extern __shared__ float smem[];
    float* Wt = smem;                 // Wt[k*129 + j] = W[j*128 + k]
    float* xs = smem + 128 * 129;     // xs[16][128]
    int t = threadIdx.x;

    for (int idx = t; idx < D * D; idx += 256) {
        int j = idx >> 7, k = idx & 127;
        Wt[k * 129 + j] = W[idx];
    }

    int team = t >> 7;     // 0 or 1
    int j = t & 127;
    int row0 = blockIdx.x * 128;

    for (int rb = row0; rb < row0 + 128; rb += 16) {
        __syncthreads();   // Wt ready (iter 0) / xs free for reuse
        for (int idx = t; idx < 16 * D; idx += 256) {
            int gr = rb + (idx >> 7);
            xs[idx] = (gr < n) ? x[(size_t)gr * D + (idx & 127)] : 0.f;
        }
        __syncthreads();

        float acc[8] = {0.f, 0.f, 0.f, 0.f, 0.f, 0.f, 0.f, 0.f};
        const float* xt = xs + team * 8 * D;
        #pragma unroll 8
        for (int k = 0; k < D; k++) {
            float wv = Wt[k * 129 + j];
            #pragma unroll
            for (int r = 0; r < 8; r++)
                acc[r] = fmaf(xt[r * D + k], wv, acc[r]);
        }
        #pragma unroll
        for (int r = 0; r < 8; r++) {
            int gr = rb + team * 8 + r;
            if (gr < n) g_h[(size_t)gr * D + j] = acc[r];
        }
    }
}

// -------- scatter: out[col] += (dinv[row]*dinv[col]) * h[row], one warp per edge --------
__global__ void scatter_kernel(float* __restrict__ out, int E) {
    int warp = (blockIdx.x * blockDim.x + threadIdx.x) >> 5;
    int lane = threadIdx.x & 31;
    if (warp >= E) return;
    int r = g_rows[warp];
    int c = g_cols[warp];
    float norm = g_dinv[r] * g_dinv[c];
    const float4 v = *reinterpret_cast<const float4*>(g_h + ((size_t)r << 7) + (lane << 2));
    float a = v.x * norm, b = v.y * norm, cc = v.z * norm, d = v.w * norm;
    float* dst = out + ((size_t)c << 7) + (lane << 2);
    asm volatile("red.global.add.v4.f32 [%0], {%1, %2, %3, %4};"
                 :: "l"(dst), "f"(a), "f"(b), "f"(cc), "f"(d) : "memory");
}

// -------- per-column sums for BN --------
__global__ void reduce_kernel(const float* __restrict__ agg, int n) {
    int d = threadIdx.x & 127;
    int rsub = threadIdx.x >> 7;   // 0..3 (512 threads)
    float s = 0.f, s2 = 0.f;
    for (int row = blockIdx.x * 4 + rsub; row < n; row += gridDim.x * 4) {
        float v = agg[(size_t)row * D + d];
        s += v; s2 += v * v;
    }
    atomicAdd(&g_sum[d], s);
    atomicAdd(&g_sumsq[d], s2);
}

__global__ void stats_kernel(const float* __restrict__ gamma, int n) {
    int d = threadIdx.x;
    float inv_n = 1.0f / (float)n;
    float mean = g_sum[d] * inv_n;
    float var = g_sumsq[d] * inv_n - mean * mean;
    g_mean[d] = mean;                       // bias cancels exactly through mean subtraction
    g_scale[d] = rsqrtf(var + 1e-5f) * gamma[d];
}

// -------- epilogue: out = relu((agg-mean)*scale + beta) + x --------
__global__ void final_kernel(float* __restrict__ out, const float* __restrict__ x,
                             const float* __restrict__ beta, int n) {
    int idx = blockIdx.x * blockDim.x + threadIdx.x;  // float4 index
    if (idx >= n * 32) return;
    int d4 = (idx & 31) << 2;
    float4 a = reinterpret_cast<float4*>(out)[idx];
    float4 xv = reinterpret_cast<const float4*>(x)[idx];
    a.x = fmaxf((a.x - g_mean[d4 + 0]) * g_scale[d4 + 0] + beta[d4 + 0], 0.f) + xv.x;
    a.y = fmaxf((a.y - g_mean[d4 + 1]) * g_scale[d4 + 1] + beta[d4 + 1], 0.f) + xv.y;
    a.z = fmaxf((a.z - g_mean[d4 + 2]) * g_scale[d4 + 2] + beta[d4 + 2], 0.f) + xv.z;
    a.w = fmaxf((a.w - g_mean[d4 + 3]) * g_scale[d4 + 3] + beta[d4 + 3], 0.f) + xv.w;
    reinterpret_cast<float4*>(out)[idx] = a;
}

extern "C" void kernel_launch(void* const* d_in, const int* in_sizes, int n_in,
                              void* d_out, int out_size) {
    // inputs: x[N*D] f32, edge_index[2*E] (int32 or int64), W[D*D] f32,
    //         bias[D] f32 (cancels through BN), bn_gamma[D], bn_beta[D], bit_sum (unused)
    const float* x     = (const float*)d_in[0];
    const void*  ei    = d_in[1];
    const float* W     = (const float*)d_in[2];
    const float* gamma = (const float*)d_in[4];
    const float* beta  = (const float*)d_in[5];
    int n = in_sizes[0] / D;
    int E = in_sizes[1] / 2;
    float* out = (float*)d_out;

    // zero entire output (also zeroes any trailing tuple-scalar slot)
    cudaMemsetAsync(out, 0, (size_t)out_size * sizeof(float), 0);
    zero_kernel<<<(n + 255) / 256, 256>>>(n);
    detect_kernel<<<1, 32>>>((const unsigned int*)ei);
    convert_kernel<<<(E + 255) / 256, 256>>>(ei, E);
    deg_kernel<<<(E + 255) / 256, 256>>>(E);
    dinv_kernel<<<(n + 255) / 256, 256>>>(n);

    cudaFuncSetAttribute(gemm_kernel, cudaFuncAttributeMaxDynamicSharedMemorySize, GEMM_SMEM);
    gemm_kernel<<<(n + 127) / 128, 256, GEMM_SMEM>>>(x, W, n);

    scatter_kernel<<<((size_t)E * 32 + 255) / 256, 256>>>(out, E);
    reduce_kernel<<<512, 512>>>(out, n);
    stats_kernel<<<1, 128>>>(gamma, n);
    final_kernel<<<(n * 32 + 255) / 256, 256>>>(out, x, beta, n);
}

// round 4
// speedup vs baseline: 1.8549x; 1.8549x over previous
#include <cuda_runtime.h>
#include <cstdint>

#define D 128
#define NMAX 100000
#define EMAX 800000

// -------- scratch (device globals; no allocations allowed) --------
__device__ float g_h[(size_t)NMAX * D];   // x @ W^T
__device__ float g_deg[NMAX];
__device__ float g_dinv[NMAX];
__device__ int   g_rows[EMAX];
__device__ int   g_cols[EMAX];
__device__ float g_sum[D];
__device__ float g_sumsq[D];
__device__ float g_mean[D];
__device__ float g_scale[D];
__device__ int   g_is64;

// -------- edge dtype detection (int64 vs int32) --------
// Node ids are < 2^31. int64 layout => every odd 32-bit word (high half) is 0.
// int32 layout => odd words are random node ids (P(all 64 zero) ~ 0).
__global__ void detect_kernel(const unsigned int* __restrict__ w) {
    if (threadIdx.x == 0) {
        int is64 = 1;
        for (int i = 1; i < 128; i += 2)
            if (w[i] != 0u) { is64 = 0; break; }
        g_is64 = is64;
    }
}

// -------- zero scratch (must precede convert: deg atomics fused there) --------
__global__ void zero_kernel(int n) {
    int i = blockIdx.x * blockDim.x + threadIdx.x;
    if (i < n) g_deg[i] = 0.f;
    if (i < D) { g_sum[i] = 0.f; g_sumsq[i] = 0.f; }
}

// -------- convert edges to int32 staging + fused degree histogram --------
__global__ void convert_kernel(const void* __restrict__ ei, int E) {
    int e = blockIdx.x * blockDim.x + threadIdx.x;
    if (e >= E) return;
    int r, c;
    if (g_is64) {
        const long long* p = (const long long*)ei;
        r = (int)p[e];
        c = (int)p[(size_t)E + e];
    } else {
        const int* p = (const int*)ei;
        r = p[e];
        c = p[(size_t)E + e];
    }
    g_rows[e] = r;
    g_cols[e] = c;
    atomicAdd(&g_deg[c], 1.0f);   // degree over destination (col)
}

__global__ void dinv_kernel(int n) {
    int i = blockIdx.x * blockDim.x + threadIdx.x;
    if (i < n) {
        float d = g_deg[i];
        g_dinv[i] = (d > 0.f) ? rsqrtf(d) : 0.f;
    }
}

// -------- GEMM: h = x @ W^T -----------------------------------------------
// h[i][j] = sum_k x[i][k] * W[j][k].  128x128 output tile per CTA, 256 thr,
// each thread computes an 8x8 register tile: 4 LDS.128 feed 64 FFMA per k.
// Wt[k*132+j] = W[j][k] (transposed, pad 132 keeps 16B align + kills bank
// conflicts). x staged transposed per 32-k chunk: xsT[k*132+i].
#define WT_STRIDE 132
#define GEMM_SMEM ((128 * WT_STRIDE + 32 * WT_STRIDE) * 4)
__global__ __launch_bounds__(256, 2)
void gemm_kernel(const float* __restrict__ x, const float* __restrict__ W, int n) {
    extern __shared__ float smem[];
    float* Wt  = smem;                       // [128][132]
    float* xsT = smem + 128 * WT_STRIDE;     // [32][132]
    int t  = threadIdx.x;
    int tx = t & 15;      // col group: cols tx*8 .. tx*8+7
    int ty = t >> 4;      // row group: rows ty*8 .. ty*8+7
    int row0 = blockIdx.x * 128;

    // W[j*128+k] -> Wt[k*132+j]
    for (int idx = t; idx < D * D; idx += 256) {
        int j = idx >> 7, k = idx & 127;
        Wt[k * WT_STRIDE + j] = W[idx];
    }

    float acc[8][8] = {};

    for (int kc = 0; kc < D; kc += 32) {
        __syncthreads();   // Wt ready (iter 0) / xsT free for reuse
        // stage x[row0..row0+127][kc..kc+31] transposed: 1024 float4, 4/thread
        for (int i = t; i < 1024; i += 256) {
            int r  = i >> 3;       // 0..127
            int kq = i & 7;        // float4 index within chunk
            int gr = row0 + r;
            float4 v = make_float4(0.f, 0.f, 0.f, 0.f);
            if (gr < n) v = *(const float4*)(x + (size_t)gr * D + kc + kq * 4);
            xsT[(kq * 4 + 0) * WT_STRIDE + r] = v.x;
            xsT[(kq * 4 + 1) * WT_STRIDE + r] = v.y;
            xsT[(kq * 4 + 2) * WT_STRIDE + r] = v.z;
            xsT[(kq * 4 + 3) * WT_STRIDE + r] = v.w;
        }
        __syncthreads();

        #pragma unroll 8
        for (int k = 0; k < 32; k++) {
            float a[8], b[8];
            *(float4*)&a[0] = *(const float4*)&xsT[k * WT_STRIDE + ty * 8];
            *(float4*)&a[4] = *(const float4*)&xsT[k * WT_STRIDE + ty * 8 + 4];
            *(float4*)&b[0] = *(const float4*)&Wt[(kc + k) * WT_STRIDE + tx * 8];
            *(float4*)&b[4] = *(const float4*)&Wt[(kc + k) * WT_STRIDE + tx * 8 + 4];
            #pragma unroll
            for (int i = 0; i < 8; i++)
                #pragma unroll
                for (int j = 0; j < 8; j++)
                    acc[i][j] = fmaf(a[i], b[j], acc[i][j]);
        }
    }

    #pragma unroll
    for (int i = 0; i < 8; i++) {
        int gr = row0 + ty * 8 + i;
        if (gr < n) {
            float4* dst = (float4*)(g_h + (size_t)gr * D + tx * 8);
            dst[0] = *(float4*)&acc[i][0];
            dst[1] = *(float4*)&acc[i][4];
        }
    }
}

// -------- scatter: out[col] += (dinv[row]*dinv[col]) * h[row] --------------
// One warp per 2 edges (independent chains -> MLP), red.global.add.v4.f32.
__global__ void scatter_kernel(float* __restrict__ out, int E) {
    int warp = (blockIdx.x * blockDim.x + threadIdx.x) >> 5;
    int lane = threadIdx.x & 31;
    int e0 = warp * 2;
    if (e0 >= E) return;
    int e1 = e0 + 1;
    bool has1 = (e1 < E);

    int r0 = g_rows[e0], c0 = g_cols[e0];
    int r1 = has1 ? g_rows[e1] : r0;
    int c1 = has1 ? g_cols[e1] : c0;
    float n0 = g_dinv[r0] * g_dinv[c0];
    float n1 = g_dinv[r1] * g_dinv[c1];
    float4 v0 = *(const float4*)(g_h + ((size_t)r0 << 7) + (lane << 2));
    float4 v1 = *(const float4*)(g_h + ((size_t)r1 << 7) + (lane << 2));

    float* d0 = out + ((size_t)c0 << 7) + (lane << 2);
    asm volatile("red.global.add.v4.f32 [%0], {%1, %2, %3, %4};"
                 :: "l"(d0), "f"(v0.x * n0), "f"(v0.y * n0),
                    "f"(v0.z * n0), "f"(v0.w * n0) : "memory");
    if (has1) {
        float* d1 = out + ((size_t)c1 << 7) + (lane << 2);
        asm volatile("red.global.add.v4.f32 [%0], {%1, %2, %3, %4};"
                     :: "l"(d1), "f"(v1.x * n1), "f"(v1.y * n1),
                        "f"(v1.z * n1), "f"(v1.w * n1) : "memory");
    }
}

// -------- per-column sums for BN --------
__global__ void reduce_kernel(const float* __restrict__ agg, int n) {
    int d = threadIdx.x & 127;
    int rsub = threadIdx.x >> 7;   // 0..3 (512 threads)
    float s = 0.f, s2 = 0.f;
    for (int row = blockIdx.x * 4 + rsub; row < n; row += gridDim.x * 4) {
        float v = agg[(size_t)row * D + d];
        s += v; s2 += v * v;
    }
    atomicAdd(&g_sum[d], s);
    atomicAdd(&g_sumsq[d], s2);
}

__global__ void stats_kernel(const float* __restrict__ gamma, int n) {
    int d = threadIdx.x;
    float inv_n = 1.0f / (float)n;
    float mean = g_sum[d] * inv_n;
    float var = g_sumsq[d] * inv_n - mean * mean;
    g_mean[d] = mean;                       // linear bias cancels via mean subtraction
    g_scale[d] = rsqrtf(var + 1e-5f) * gamma[d];
}

// -------- epilogue: out = relu((agg-mean)*scale + beta) + x --------
__global__ void final_kernel(float* __restrict__ out, const float* __restrict__ x,
                             const float* __restrict__ beta, int n) {
    int idx = blockIdx.x * blockDim.x + threadIdx.x;  // float4 index
    if (idx >= n * 32) return;
    int d4 = (idx & 31) << 2;
    float4 a = reinterpret_cast<float4*>(out)[idx];
    float4 xv = reinterpret_cast<const float4*>(x)[idx];
    a.x = fmaxf((a.x - g_mean[d4 + 0]) * g_scale[d4 + 0] + beta[d4 + 0], 0.f) + xv.x;
    a.y = fmaxf((a.y - g_mean[d4 + 1]) * g_scale[d4 + 1] + beta[d4 + 1], 0.f) + xv.y;
    a.z = fmaxf((a.z - g_mean[d4 + 2]) * g_scale[d4 + 2] + beta[d4 + 2], 0.f) + xv.z;
    a.w = fmaxf((a.w - g_mean[d4 + 3]) * g_scale[d4 + 3] + beta[d4 + 3], 0.f) + xv.w;
    reinterpret_cast<float4*>(out)[idx] = a;
}

extern "C" void kernel_launch(void* const* d_in, const int* in_sizes, int n_in,
                              void* d_out, int out_size) {
    // inputs: x[N*D] f32, edge_index[2*E] (int32 or int64), W[D*D] f32,
    //         bias[D] (cancels through BN), bn_gamma[D], bn_beta[D], bit_sum
    const float* x     = (const float*)d_in[0];
    const void*  ei    = d_in[1];
    const float* W     = (const float*)d_in[2];
    const float* gamma = (const float*)d_in[4];
    const float* beta  = (const float*)d_in[5];
    int n = in_sizes[0] / D;
    int E = in_sizes[1] / 2;
    float* out = (float*)d_out;

    cudaMemsetAsync(out, 0, (size_t)out_size * sizeof(float), 0);
    zero_kernel<<<(n + 255) / 256, 256>>>(n);
    detect_kernel<<<1, 32>>>((const unsigned int*)ei);
    convert_kernel<<<(E + 255) / 256, 256>>>(ei, E);   // fused degree
    dinv_kernel<<<(n + 255) / 256, 256>>>(n);

    cudaFuncSetAttribute(gemm_kernel, cudaFuncAttributeMaxDynamicSharedMemorySize, GEMM_SMEM);
    gemm_kernel<<<(n + 127) / 128, 256, GEMM_SMEM>>>(x, W, n);

    int warps = (E + 1) / 2;
    scatter_kernel<<<((size_t)warps * 32 + 255) / 256, 256>>>(out, E);
    reduce_kernel<<<512, 512>>>(out, n);
    stats_kernel<<<1, 128>>>(gamma, n);
    final_kernel<<<(n * 32 + 255) / 256, 256>>>(out, x, beta, n);
}